// round 6
// baseline (speedup 1.0000x reference)
#include <cuda_runtime.h>
#include <math.h>

#define TT 512
#define BB 256
#define DD 256
#define HH 256
#define KK 256
#define GG 1024  // 4*H

#define NBLK 256     // persistent grid: 8 batch-blocks x 32 col-blocks
#define NTHR 256

// Scratch state (static device globals: allocation-free per harness rules)
__device__ float g_gx[(size_t)TT * BB * GG];   // precomputed x-path gates + biases
__device__ float g_hm[2][BB * HH];             // double-buffered (h .* mask_h)
__device__ unsigned g_bar = 0;                 // grid barrier counter
__device__ unsigned g_gen = 0;                 // grid barrier generation

// ---------------------------------------------------------------------------
// gemm_x: g_gx[m, n] = sum_k X[m,k]*MX[m&255,k]*W[n,k] + bih[n] + bhh[n]
// ---------------------------------------------------------------------------
__global__ __launch_bounds__(256) void gemm_x_kernel(
    const float* __restrict__ X, const float* __restrict__ MX,
    const float* __restrict__ W, const float* __restrict__ bih,
    const float* __restrict__ bhh)
{
    __shared__ float As[8][132];
    __shared__ float Bs[8][132];
    const int m0 = blockIdx.x * 128;
    const int n0 = blockIdx.y * 128;
    const int tid = threadIdx.x;

    const int lr = tid >> 1;
    const int lk = (tid & 1) * 4;
    const int tx = tid & 15;
    const int ty = tid >> 4;

    float acc[8][8];
#pragma unroll
    for (int i = 0; i < 8; i++)
#pragma unroll
        for (int j = 0; j < 8; j++) acc[i][j] = 0.0f;

    const int mrow = m0 + lr;
    const int mxrow = mrow & (BB - 1);

    for (int k0 = 0; k0 < KK; k0 += 8) {
        float4 xa = *(const float4*)(X + (size_t)mrow * KK + k0 + lk);
        float4 ma = *(const float4*)(MX + (size_t)mxrow * KK + k0 + lk);
        As[lk + 0][lr] = xa.x * ma.x;
        As[lk + 1][lr] = xa.y * ma.y;
        As[lk + 2][lr] = xa.z * ma.z;
        As[lk + 3][lr] = xa.w * ma.w;
        float4 wb = *(const float4*)(W + (size_t)(n0 + lr) * KK + k0 + lk);
        Bs[lk + 0][lr] = wb.x;
        Bs[lk + 1][lr] = wb.y;
        Bs[lk + 2][lr] = wb.z;
        Bs[lk + 3][lr] = wb.w;
        __syncthreads();

#pragma unroll
        for (int k = 0; k < 8; k++) {
            float4 a0 = *(const float4*)&As[k][ty * 8];
            float4 a1 = *(const float4*)&As[k][ty * 8 + 4];
            float4 b0 = *(const float4*)&Bs[k][tx * 8];
            float4 b1 = *(const float4*)&Bs[k][tx * 8 + 4];
            float av[8] = {a0.x, a0.y, a0.z, a0.w, a1.x, a1.y, a1.z, a1.w};
            float bv[8] = {b0.x, b0.y, b0.z, b0.w, b1.x, b1.y, b1.z, b1.w};
#pragma unroll
            for (int i = 0; i < 8; i++)
#pragma unroll
                for (int j = 0; j < 8; j++) acc[i][j] += av[i] * bv[j];
        }
        __syncthreads();
    }

    float bsum[8];
#pragma unroll
    for (int j = 0; j < 8; j++) {
        int n = n0 + tx * 8 + j;
        bsum[j] = bih[n] + bhh[n];
    }
#pragma unroll
    for (int i = 0; i < 8; i++) {
        size_t base = (size_t)(m0 + ty * 8 + i) * GG + n0 + tx * 8;
        float4 s0 = make_float4(acc[i][0] + bsum[0], acc[i][1] + bsum[1],
                                acc[i][2] + bsum[2], acc[i][3] + bsum[3]);
        float4 s1 = make_float4(acc[i][4] + bsum[4], acc[i][5] + bsum[5],
                                acc[i][6] + bsum[6], acc[i][7] + bsum[7]);
        *(float4*)&g_gx[base] = s0;
        *(float4*)&g_gx[base + 4] = s1;
    }
}

// ---------------------------------------------------------------------------
// Grid-wide barrier. Co-residency: __launch_bounds__(NTHR, 2) -> 2 CTAs/SM,
// 296 slots >= 256 blocks.
// ---------------------------------------------------------------------------
__device__ __forceinline__ void grid_barrier()
{
    __threadfence();          // drain hm stores to L2
    __syncthreads();
    if (threadIdx.x == 0) {
        unsigned gen = *(volatile unsigned*)&g_gen;   // read BEFORE arriving
        if (atomicAdd(&g_bar, 1u) == (unsigned)(NBLK - 1)) {
            g_bar = 0;
            __threadfence();
            *(volatile unsigned*)&g_gen = gen + 1;    // release
        } else {
            while (*(volatile unsigned*)&g_gen == gen) { }
        }
    }
    __syncthreads();
}

// Fast, overflow-safe transcendentals (~2-ulp __expf; 1e-3 budget has 100x room)
__device__ __forceinline__ float fsig(float x) {
    return __fdividef(1.0f, 1.0f + __expf(-x));
}
__device__ __forceinline__ float ftanh(float x) {
    return __fdividef(2.0f, 1.0f + __expf(-2.0f * x)) - 1.0f;
}

// ---------------------------------------------------------------------------
// Persistent recurrent kernel, 256 thr/CTA (~14 warps/SM for latency hiding).
//   Grid 256 = 8 batch-blocks (32 rows) x 32 col-blocks (8 h-cols x 4 gates).
//   Thread (tx,ty): j = j0+tx, row = b0+ty; owns 4 gate accumulators and the
//   (row,j) cell state in registers. Per k: LDS.32 broadcast (a) + LDS.128
//   (4 gate weights) + 4 FFMA. gx(t+1) prefetched before the grid barrier.
// ---------------------------------------------------------------------------
__global__ __launch_bounds__(NTHR, 2) void recurrent_kernel(
    const float* __restrict__ mh, const float* __restrict__ Whh,
    const int* __restrict__ bsz, const float* __restrict__ h0,
    const float* __restrict__ c0, float* __restrict__ out)
{
    __shared__ float Ws[KK][8][4];        // [k][jlocal][gate] = 32 KB
    __shared__ float As[2][32][33];       // hm k-chunk [k][row], double-buffered
    __shared__ int   Sbsz[TT];            // 2 KB

    const int bb = blockIdx.x >> 5;       // 0..7
    const int cb = blockIdx.x & 31;       // 0..31
    const int b0 = bb * 32;
    const int j0 = cb * 8;
    const int tid = threadIdx.x;
    const int tx = tid & 7;               // h-col
    const int ty = tid >> 3;              // row 0..31
    const int row = b0 + ty;
    const int j = j0 + tx;

    // ---- one-time: W_hh slice -> smem as [k][jl][gate] ----
    for (int rr = tid >> 5; rr < 32; rr += 8) {       // 8 warps over 32 (g,jl) rows
        int g = rr >> 3, jl = rr & 7;
        const float* src = Whh + (size_t)(g * 256 + j0 + jl) * KK;
        for (int k = (tid & 31); k < KK; k += 32)
            Ws[k][jl][g] = src[k];
    }
    for (int i = tid; i < TT; i += NTHR) Sbsz[i] = bsz[i];

    // ---- one-time: register state (1 row per thread) ----
    float mhv = mh[row * HH + j];
    float cc = c0[row * HH + j];
    float hh = h0[row * HH + j];
    g_hm[0][row * HH + j] = hh * mhv;
    __syncthreads();
    grid_barrier();     // hm[0] visible everywhere; Ws/Sbsz ready

    // chunk loader: 32 rows x 32 k = 1024 floats, one float4 per thread
    const int lr = tid >> 3;              // row 0..31
    const int lk = (tid & 7) * 4;         // k offset within chunk
    const size_t hoff = (size_t)(b0 + lr) * HH + lk;

    // prefetch gx(0)
    float a0, a1, a2, a3;
    {
        const float* gp = g_gx + (size_t)row * GG + j;
        a0 = __ldcg(gp);        a1 = __ldcg(gp + 256);
        a2 = __ldcg(gp + 512);  a3 = __ldcg(gp + 768);
    }

    for (int t = 0; t < TT; t++) {
        const float* __restrict__ hmp = g_hm[t & 1];
        float* __restrict__ hmn = g_hm[(t & 1) ^ 1];
        const float* hrow = hmp + hoff;

        // preload chunk 0
        float4 p = __ldcg((const float4*)(hrow));
        As[0][lk + 0][lr] = p.x;
        As[0][lk + 1][lr] = p.y;
        As[0][lk + 2][lr] = p.z;
        As[0][lk + 3][lr] = p.w;
        __syncthreads();

#pragma unroll
        for (int c = 0; c < 8; c++) {
            const int buf = c & 1;
            if (c < 7)   // prefetch next chunk (hidden under compute)
                p = __ldcg((const float4*)(hrow + (c + 1) * 32));
            const int kb = c * 32;
#pragma unroll
            for (int k = 0; k < 32; k++) {
                const float a = As[buf][k][ty];
                const float4 w = *(const float4*)&Ws[kb + k][tx][0];
                a0 = fmaf(a, w.x, a0); a1 = fmaf(a, w.y, a1);
                a2 = fmaf(a, w.z, a2); a3 = fmaf(a, w.w, a3);
            }
            if (c < 7) {   // store prefetch into the buffer nobody reads yet
                As[buf ^ 1][lk + 0][lr] = p.x;
                As[buf ^ 1][lk + 1][lr] = p.y;
                As[buf ^ 1][lk + 2][lr] = p.z;
                As[buf ^ 1][lk + 3][lr] = p.w;
                __syncthreads();   // one sync per chunk
            }
        }

        // pointwise LSTM (1 owned row); hm store on critical path, out deferred
        const int size = Sbsz[t];
        float o0;
        {
            float iv = fsig(a0), fv = fsig(a1), gv = ftanh(a2), ov = fsig(a3);
            float cn = fv * cc + iv * gv;
            float hn = ov * ftanh(cn);
            bool act = row < size;
            if (act) { cc = cn; hh = hn; }
            o0 = act ? hn : 0.0f;
            hmn[row * HH + j] = hh * mhv;
        }

        // prefetch gx(t+1): independent of the barrier, hides L2/DRAM latency
        if (t + 1 < TT) {
            const float* gp = g_gx + ((size_t)(t + 1) * BB + row) * GG + j;
            a0 = __ldcg(gp);        a1 = __ldcg(gp + 256);
            a2 = __ldcg(gp + 512);  a3 = __ldcg(gp + 768);
        }

        grid_barrier();

        // out store after the barrier: fence above doesn't wait on it
        out[((size_t)t * BB + row) * HH + j] = o0;
    }

    // final hn, cn
    const size_t TBH = (size_t)TT * BB * HH;
    out[TBH + row * HH + j] = hh;
    out[TBH + BB * HH + row * HH + j] = cc;
}

// ---------------------------------------------------------------------------
extern "C" void kernel_launch(void* const* d_in, const int* in_sizes, int n_in,
                              void* d_out, int out_size)
{
    const float* X   = (const float*)d_in[0];   // [T,B,D]
    const float* h0  = (const float*)d_in[1];   // [B,H]
    const float* c0  = (const float*)d_in[2];   // [B,H]
    const float* mx  = (const float*)d_in[3];   // [B,D]
    const float* mh  = (const float*)d_in[4];   // [B,H]
    const float* Wih = (const float*)d_in[5];   // [4H,D]
    const float* Whh = (const float*)d_in[6];   // [4H,H]
    const float* bih = (const float*)d_in[7];   // [4H]
    const float* bhh = (const float*)d_in[8];   // [4H]
    const int*   bsz = (const int*)d_in[9];     // [T]
    float* out = (float*)d_out;                 // [T*B*H] ++ [B*H] ++ [B*H]

    gemm_x_kernel<<<dim3((TT * BB) / 128, GG / 128), 256>>>(X, mx, Wih, bih, bhh);
    recurrent_kernel<<<NBLK, NTHR>>>(mh, Whh, bsz, h0, c0, out);
}

// round 10
// speedup vs baseline: 1.4632x; 1.4632x over previous
#include <cuda_runtime.h>
#include <math.h>

#define TT 512
#define BB 256
#define DD 256
#define HH 256
#define KK 256
#define GG 1024  // 4*H

#define NBLK 256     // persistent grid for recurrence
#define NTHR 128

// Scratch state (static device globals: allocation-free per harness rules)
__device__ float g_gx[(size_t)TT * BB * GG];   // precomputed x-path gates + biases
__device__ float g_hm[2][BB * HH];             // double-buffered (h .* mask_h)
__device__ unsigned g_bar = 0;                 // grid barrier counter
__device__ unsigned g_gen = 0;                 // grid barrier generation

// ===========================================================================
// Split-tf32 helpers (sm_80+ mma.sync — valid on sm_100a; NO sm_103a ISA)
// ===========================================================================
__device__ __forceinline__ unsigned f2tf(float a) {
    unsigned r;
    asm("cvt.rna.tf32.f32 %0, %1;" : "=r"(r) : "f"(a));
    return r;
}
__device__ __forceinline__ void split_tf32(float a, unsigned& h, unsigned& l) {
    h = f2tf(a);                                // high ~11 mantissa bits
    l = f2tf(a - __uint_as_float(h));           // next ~11 bits (residual)
}
__device__ __forceinline__ void mma_tf32(float* c, const unsigned* a,
                                         unsigned b0, unsigned b1) {
    asm("mma.sync.aligned.m16n8k8.row.col.f32.tf32.tf32.f32 "
        "{%0,%1,%2,%3}, {%4,%5,%6,%7}, {%8,%9}, {%0,%1,%2,%3};"
        : "+f"(c[0]), "+f"(c[1]), "+f"(c[2]), "+f"(c[3])
        : "r"(a[0]), "r"(a[1]), "r"(a[2]), "r"(a[3]), "r"(b0), "r"(b1));
}

// ---------------------------------------------------------------------------
// gemm_x (tensor cores, split-tf32 3-term => fp32-level accuracy):
//   g_gx[m,n] = sum_k X[m,k]*MX[m&255,k] * W[n,k] + bih[n] + bhh[n]
//   M=131072, N=1024, K=256. CTA tile 128x64, 8 warps of 16x64.
//   Fragment LDS conflict-free via stride-36 padding (bank = g*4+tg+c).
// ---------------------------------------------------------------------------
__global__ __launch_bounds__(256) void gemm_x_tc(
    const float* __restrict__ X, const float* __restrict__ MX,
    const float* __restrict__ W, const float* __restrict__ bih,
    const float* __restrict__ bhh)
{
    __shared__ float As[128][36];   // [m][k] chunk, 18 KB
    __shared__ float Bs[64][36];    // [n][k] chunk,  9 KB

    const int m0 = blockIdx.x * 128;
    const int n0 = blockIdx.y * 64;
    const int tid = threadIdx.x;
    const int warp = tid >> 5;
    const int lane = tid & 31;
    const int g = lane >> 2;        // 0..7
    const int tg = lane & 3;        // 0..3
    const int wm = warp * 16;       // warp's M offset within CTA tile

    float acc[8][4];
#pragma unroll
    for (int nt = 0; nt < 8; nt++)
#pragma unroll
        for (int i = 0; i < 4; i++) acc[nt][i] = 0.0f;

    for (int kc = 0; kc < 8; kc++) {
        const int k0 = kc * 32;
        __syncthreads();
        // load A chunk: 128 rows x 32 k, one float4 x4 per thread, masked by MX
#pragma unroll
        for (int q = 0; q < 4; q++) {
            int i = tid + 256 * q;          // 0..1023 float4 slots
            int row = i >> 3;               // 8 float4 per row
            int kq = (i & 7) * 4;
            float4 xv = *(const float4*)(X + (size_t)(m0 + row) * KK + k0 + kq);
            float4 mv = *(const float4*)(MX + (size_t)((m0 + row) & (BB - 1)) * KK + k0 + kq);
            xv.x *= mv.x; xv.y *= mv.y; xv.z *= mv.z; xv.w *= mv.w;
            *(float4*)&As[row][kq] = xv;
        }
        // load B chunk: 64 rows x 32 k, one float4 x2 per thread
#pragma unroll
        for (int q = 0; q < 2; q++) {
            int i = tid + 256 * q;          // 0..511
            int row = i >> 3;
            int kq = (i & 7) * 4;
            *(float4*)&Bs[row][kq] =
                *(const float4*)(W + (size_t)(n0 + row) * KK + k0 + kq);
        }
        __syncthreads();

#pragma unroll
        for (int ks = 0; ks < 4; ks++) {
            const int kk = ks * 8;
            // A fragment (m16 x k8), split hi/lo
            unsigned ah[4], al[4];
            split_tf32(As[wm + g][kk + tg],         ah[0], al[0]);
            split_tf32(As[wm + g + 8][kk + tg],     ah[1], al[1]);
            split_tf32(As[wm + g][kk + tg + 4],     ah[2], al[2]);
            split_tf32(As[wm + g + 8][kk + tg + 4], ah[3], al[3]);
#pragma unroll
            for (int nt = 0; nt < 8; nt++) {
                unsigned bh0, bl0, bh1, bl1;
                split_tf32(Bs[nt * 8 + g][kk + tg],     bh0, bl0);
                split_tf32(Bs[nt * 8 + g][kk + tg + 4], bh1, bl1);
                mma_tf32(acc[nt], ah, bh0, bh1);   // hi*hi
                mma_tf32(acc[nt], ah, bl0, bl1);   // hi*lo
                mma_tf32(acc[nt], al, bh0, bh1);   // lo*hi
            }
        }
    }

    // epilogue: add biases, store float2 pairs
#pragma unroll
    for (int nt = 0; nt < 8; nt++) {
        const int n = n0 + nt * 8 + tg * 2;
        const float bs0 = bih[n] + bhh[n];
        const float bs1 = bih[n + 1] + bhh[n + 1];
        const int m = m0 + wm + g;
        float2 r0 = make_float2(acc[nt][0] + bs0, acc[nt][1] + bs1);
        float2 r1 = make_float2(acc[nt][2] + bs0, acc[nt][3] + bs1);
        *(float2*)&g_gx[(size_t)m * GG + n] = r0;
        *(float2*)&g_gx[(size_t)(m + 8) * GG + n] = r1;
    }
}

// ---------------------------------------------------------------------------
// Grid-wide barrier (R5-proven form). Co-residency: __launch_bounds__(NTHR,2).
// ---------------------------------------------------------------------------
__device__ __forceinline__ void grid_barrier()
{
    __threadfence();          // drain hm stores to L2
    __syncthreads();
    if (threadIdx.x == 0) {
        unsigned gen = *(volatile unsigned*)&g_gen;   // read BEFORE arriving
        if (atomicAdd(&g_bar, 1u) == (unsigned)(NBLK - 1)) {
            g_bar = 0;
            __threadfence();
            *(volatile unsigned*)&g_gen = gen + 1;    // release
        } else {
            while (*(volatile unsigned*)&g_gen == gen) { }
        }
    }
    __syncthreads();
}

// Fast, overflow-safe transcendentals (~2-ulp __expf)
__device__ __forceinline__ float fsig(float x) {
    return __fdividef(1.0f, 1.0f + __expf(-x));
}
__device__ __forceinline__ float ftanh(float x) {
    return __fdividef(2.0f, 1.0f + __expf(-2.0f * x)) - 1.0f;
}

// ---------------------------------------------------------------------------
// Persistent recurrent kernel — R5 verbatim structure (proven 6546us) plus
// gx(t+1) prefetch before the barrier (proven in R6). Full grid barrier.
// ---------------------------------------------------------------------------
__global__ __launch_bounds__(NTHR, 2) void recurrent_kernel(
    const float* __restrict__ mh, const float* __restrict__ Whh,
    const int* __restrict__ bsz, const float* __restrict__ h0,
    const float* __restrict__ c0, float* __restrict__ out)
{
    __shared__ __align__(16) float Ws[KK][8][4];  // [k][jl][gate] 32 KB
    __shared__ float As[2][32][34];               // hm chunk [k][row], padded
    __shared__ int   Sbsz[TT];                    // 2 KB (total ~43 KB)

    const int bb = blockIdx.x >> 5;       // batch-block 0..7
    const int cb = blockIdx.x & 31;       // col-block 0..31
    const int b0 = bb * 32;
    const int j0 = cb * 8;
    const int tid = threadIdx.x;
    const int tx = tid & 7;               // h-col
    const int ty = tid >> 3;              // row-pair 0..15
    const int r0 = b0 + ty * 2;
    const int j = j0 + tx;

    // one-time: W_hh slice -> smem as [k][jl][gate]
    for (int rr = tid >> 5; rr < 32; rr += 4) {
        int g = rr >> 3, jl = rr & 7;
        const float* src = Whh + (size_t)(g * 256 + j0 + jl) * KK;
        for (int k = (tid & 31); k < KK; k += 32)
            Ws[k][jl][g] = src[k];
    }
    for (int i = tid; i < TT; i += NTHR) Sbsz[i] = bsz[i];

    // one-time: register state (2 rows per thread)
    float mhv[2], cc[2], hh[2];
#pragma unroll
    for (int r = 0; r < 2; r++) {
        int b = r0 + r;
        mhv[r] = mh[b * HH + j];
        cc[r] = c0[b * HH + j];
        hh[r] = h0[b * HH + j];
        g_hm[0][b * HH + j] = hh[r] * mhv[r];
    }
    __syncthreads();
    grid_barrier();     // hm[0] visible everywhere; Ws/Sbsz ready

    // chunk loader: 32 rows x 32 k, 8 floats per thread (2x float4)
    const int lr = tid >> 2;              // row 0..31
    const int lk = (tid & 3) * 8;         // k offset within chunk
    const size_t hoff = (size_t)(b0 + lr) * HH + lk;

    // prefetch gx(0) for both rows
    float gx0[4], gx1[4];
    {
        const float* gp = g_gx + (size_t)r0 * GG + j;
#pragma unroll
        for (int g = 0; g < 4; g++) {
            gx0[g] = __ldcg(gp + g * 256);
            gx1[g] = __ldcg(gp + GG + g * 256);
        }
    }

    for (int t = 0; t < TT; t++) {
        const float* __restrict__ hmp = g_hm[t & 1];
        float* __restrict__ hmn = g_hm[(t & 1) ^ 1];
        const float* hrow = hmp + hoff;

        float a00 = gx0[0], a01 = gx0[1], a02 = gx0[2], a03 = gx0[3];
        float a10 = gx1[0], a11 = gx1[1], a12 = gx1[2], a13 = gx1[3];

        // preload chunk 0
        float4 p0 = __ldcg((const float4*)(hrow + 0));
        float4 p1 = __ldcg((const float4*)(hrow + 4));
#pragma unroll
        for (int i = 0; i < 4; i++) {
            As[0][lk + i][lr] = ((const float*)&p0)[i];
            As[0][lk + 4 + i][lr] = ((const float*)&p1)[i];
        }
        __syncthreads();

#pragma unroll
        for (int c = 0; c < 8; c++) {
            const int buf = c & 1;
            if (c < 7) {   // prefetch next chunk (hidden under compute)
                p0 = __ldcg((const float4*)(hrow + (c + 1) * 32));
                p1 = __ldcg((const float4*)(hrow + (c + 1) * 32 + 4));
            }
            const int kb = c * 32;
#pragma unroll
            for (int k = 0; k < 32; k++) {
                float2 a = *(const float2*)&As[buf][k][ty * 2];
                const float4 w = *(const float4*)&Ws[kb + k][tx][0];
                a00 = fmaf(a.x, w.x, a00); a01 = fmaf(a.x, w.y, a01);
                a02 = fmaf(a.x, w.z, a02); a03 = fmaf(a.x, w.w, a03);
                a10 = fmaf(a.y, w.x, a10); a11 = fmaf(a.y, w.y, a11);
                a12 = fmaf(a.y, w.z, a12); a13 = fmaf(a.y, w.w, a13);
            }
            if (c < 7) {
#pragma unroll
                for (int i = 0; i < 4; i++) {
                    As[buf ^ 1][lk + i][lr] = ((const float*)&p0)[i];
                    As[buf ^ 1][lk + 4 + i][lr] = ((const float*)&p1)[i];
                }
                __syncthreads();   // one sync per chunk
            }
        }

        // pointwise LSTM; hm stores on critical path, out deferred
        const int size = Sbsz[t];
        float o0, o1;
        {
            float iv = fsig(a00), fv = fsig(a01), gv = ftanh(a02), ov = fsig(a03);
            float cn = fv * cc[0] + iv * gv;
            float hn = ov * ftanh(cn);
            bool act = r0 < size;
            if (act) { cc[0] = cn; hh[0] = hn; }
            o0 = act ? hn : 0.0f;
            hmn[r0 * HH + j] = hh[0] * mhv[0];
        }
        {
            float iv = fsig(a10), fv = fsig(a11), gv = ftanh(a12), ov = fsig(a13);
            float cn = fv * cc[1] + iv * gv;
            float hn = ov * ftanh(cn);
            bool act = (r0 + 1) < size;
            if (act) { cc[1] = cn; hh[1] = hn; }
            o1 = act ? hn : 0.0f;
            hmn[(r0 + 1) * HH + j] = hh[1] * mhv[1];
        }

        // prefetch gx(t+1): independent of the barrier (R6-proven)
        if (t + 1 < TT) {
            const float* gp = g_gx + ((size_t)(t + 1) * BB + r0) * GG + j;
#pragma unroll
            for (int g = 0; g < 4; g++) {
                gx0[g] = __ldcg(gp + g * 256);
                gx1[g] = __ldcg(gp + GG + g * 256);
            }
        }

        grid_barrier();

        // out stores after the barrier: fence doesn't wait on them
        out[((size_t)t * BB + r0) * HH + j] = o0;
        out[((size_t)t * BB + r0 + 1) * HH + j] = o1;
    }

    // final hn, cn
    const size_t TBH = (size_t)TT * BB * HH;
#pragma unroll
    for (int r = 0; r < 2; r++) {
        int b = r0 + r;
        out[TBH + b * HH + j] = hh[r];
        out[TBH + BB * HH + b * HH + j] = cc[r];
    }
}

// ---------------------------------------------------------------------------
extern "C" void kernel_launch(void* const* d_in, const int* in_sizes, int n_in,
                              void* d_out, int out_size)
{
    const float* X   = (const float*)d_in[0];   // [T,B,D]
    const float* h0  = (const float*)d_in[1];   // [B,H]
    const float* c0  = (const float*)d_in[2];   // [B,H]
    const float* mx  = (const float*)d_in[3];   // [B,D]
    const float* mh  = (const float*)d_in[4];   // [B,H]
    const float* Wih = (const float*)d_in[5];   // [4H,D]
    const float* Whh = (const float*)d_in[6];   // [4H,H]
    const float* bih = (const float*)d_in[7];   // [4H]
    const float* bhh = (const float*)d_in[8];   // [4H]
    const int*   bsz = (const int*)d_in[9];     // [T]
    float* out = (float*)d_out;                 // [T*B*H] ++ [B*H] ++ [B*H]

    gemm_x_tc<<<dim3((TT * BB) / 128, GG / 64), 256>>>(X, mx, Wih, bih, bhh);
    recurrent_kernel<<<NBLK, NTHR>>>(mh, Whh, bsz, h0, c0, out);
}